// round 11
// baseline (speedup 1.0000x reference)
#include <cuda_runtime.h>
#include <cuda_fp16.h>
#include <math.h>

#define BB     64
#define LATENT 128
#define EMBD   512
#define HID    1024
#define VOC    32000
#define TSTEPS 64
#define NLBLK  125          // logits CTAs (125 * 256 = 32000)
#define NCHUNK 16           // logits K chunks of 64 halves
#define NCHG   24           // gates K chunks (1536/64)
#define INV256 0.00390625f
#define CAP2   2048         // per-row candidate cap

typedef unsigned long long u64;
typedef unsigned int u32;

// ---------------- device state (no allocation) ------------------------------
__device__ float g_c[BB * HID];
__device__ float g_pval[BB * NLBLK];                       // per-block row max
__device__ int   g_tok[BB];
__device__ float g_hf[BB * HID];                           // fp32 h (refine)
__device__ int   g_ccnt[BB];                               // candidate counts
__device__ int   g_cidx[BB][CAP2];
__device__ float g_cval[BB][CAP2];
__device__ __align__(16) __half g_hhb[2][BB * HID];        // h hi ping-pong
__device__ __align__(16) __half g_hlb[2][BB * HID];        // h lo ping-pong
__device__ __align__(16) __half g_whi[(size_t)VOC * HID];  // fc_w hi
__device__ __align__(16) __half g_ehi[(size_t)VOC * EMBD]; // emb hi
__device__ __align__(16) __half g_elo[(size_t)VOC * EMBD]; // emb lo*256
__device__ __align__(16) __half g_pwhi[4096 * 1536];       // packed gate W hi
__device__ __align__(16) __half g_pwlo[4096 * 1536];       // packed gate W lo*256
__device__ float g_pb[4096];                               // packed bih+bhh

// ---------------- helpers ---------------------------------------------------
__device__ __forceinline__ u32 smem_u32(const void* p) {
    u32 a; asm("{ .reg .u64 t; cvta.to.shared.u64 t, %1; cvt.u32.u64 %0, t; }"
               : "=r"(a) : "l"(p));
    return a;
}
__device__ __forceinline__ void cpa16(u32 dst, const void* src) {
    asm volatile("cp.async.cg.shared.global [%0], [%1], 16;" :: "r"(dst), "l"(src));
}
#define CPA_COMMIT() asm volatile("cp.async.commit_group;" ::: "memory")
#define CPA_WAIT0()  asm volatile("cp.async.wait_group 0;" ::: "memory")
#define CPA_WAIT1()  asm volatile("cp.async.wait_group 1;" ::: "memory")
#define CPA_WAIT2()  asm volatile("cp.async.wait_group 2;" ::: "memory")

__device__ __forceinline__ void ldm4(u32* r, u32 addr) {
    asm volatile("ldmatrix.sync.aligned.m8n8.x4.shared.b16 {%0,%1,%2,%3}, [%4];"
        : "=r"(r[0]), "=r"(r[1]), "=r"(r[2]), "=r"(r[3]) : "r"(addr));
}
__device__ __forceinline__ void mma16816(float* d, const u32* a, const u32* b) {
    asm volatile("mma.sync.aligned.m16n8k16.row.col.f32.f16.f16.f32 "
        "{%0,%1,%2,%3}, {%4,%5,%6,%7}, {%8,%9}, {%0,%1,%2,%3};"
        : "+f"(d[0]), "+f"(d[1]), "+f"(d[2]), "+f"(d[3])
        : "r"(a[0]), "r"(a[1]), "r"(a[2]), "r"(a[3]), "r"(b[0]), "r"(b[1]));
}

#define SWZ(o) ((o) ^ (((o) >> 3) & 0x70))

// logits SMEM: hdr 4096 (bias 1024 | spv 2048 | brmax 256) + 3 buffers of 48K
#define AHI_OFF  0
#define ALO_OFF  8192
#define BHI_OFF  16384
#define BUFSTR   49152
#define HDR      4096
#define DSMEM    (1024 + HDR + 3 * BUFSTR)

// gates SMEM: hdr 512 (stok 256 | bias 128) + 4 buffers of 24K
#define GAHI 0
#define GALO 8192
#define GBHI 16384
#define GBLO 20480
#define GBUF 24576
#define GHDR 512
#define GDSM (1024 + GHDR + 4 * GBUF)

// ---------------- init: h = z @ lth_w^T + lth_b -> buf 0 --------------------
__global__ void k_init(const float* __restrict__ z,
                       const float* __restrict__ lw,
                       const float* __restrict__ lb) {
    int idx = blockIdx.x * 256 + threadIdx.x;
    int r = idx >> 10;
    int u = idx & (HID - 1);
    float s = lb[u];
    const float* zr = z + r * LATENT;
    const float* wr = lw + (size_t)u * LATENT;
    #pragma unroll 8
    for (int k = 0; k < LATENT; k++) s += zr[k] * wr[k];
    g_c[idx] = 0.f;
    __half hh = __float2half_rn(s);
    g_hhb[0][idx] = hh;
    g_hlb[0][idx] = __float2half_rn((s - __half2float(hh)) * 256.0f);
    if (idx < BB) g_tok[idx] = 0;
}

// ---------------- prep A: fc_w hi + emb hi/lo --------------------------------
__global__ void __launch_bounds__(256, 1)
k_prepA(const float* __restrict__ fcw, const float* __restrict__ emb) {
    const int bid = blockIdx.x;
    const int tid = threadIdx.x;
    if (bid < 32000) {
        size_t i4 = (size_t)bid * 1024 + tid * 4;
        float4 w = *(const float4*)&fcw[i4];
        *(__half2*)&g_whi[i4]     = __halves2half2(__float2half_rn(w.x), __float2half_rn(w.y));
        *(__half2*)&g_whi[i4 + 2] = __halves2half2(__float2half_rn(w.z), __float2half_rn(w.w));
    } else {
        size_t i4 = (size_t)(bid - 32000) * 1024 + tid * 4;
        float4 w = *(const float4*)&emb[i4];
        __half h0 = __float2half_rn(w.x), h1 = __float2half_rn(w.y);
        __half h2 = __float2half_rn(w.z), h3 = __float2half_rn(w.w);
        *(__half2*)&g_ehi[i4]     = __halves2half2(h0, h1);
        *(__half2*)&g_ehi[i4 + 2] = __halves2half2(h2, h3);
        *(__half2*)&g_elo[i4]     = __halves2half2(
            __float2half_rn((w.x - __half2float(h0)) * 256.f),
            __float2half_rn((w.y - __half2float(h1)) * 256.f));
        *(__half2*)&g_elo[i4 + 2] = __halves2half2(
            __float2half_rn((w.z - __half2float(h2)) * 256.f),
            __float2half_rn((w.w - __half2float(h3)) * 256.f));
    }
}

// ---------------- prep B: packed gate weights + bias -------------------------
__global__ void __launch_bounds__(384, 1)
k_prepB(const float* __restrict__ wih, const float* __restrict__ whh,
        const float* __restrict__ bih, const float* __restrict__ bhh) {
    int cn = blockIdx.x;                 // 0..4095
    int c = cn >> 5, n = cn & 31;
    int g = n >> 3, j = n & 7;
    int orow = g * 1024 + c * 8 + j;
    int k0 = threadIdx.x * 4;            // 0..1532
    float4 w = (k0 < 512)
        ? *(const float4*)&wih[(size_t)orow * EMBD + k0]
        : *(const float4*)&whh[(size_t)orow * HID + k0 - 512];
    size_t d = (size_t)cn * 1536 + k0;
    __half h0 = __float2half_rn(w.x), h1 = __float2half_rn(w.y);
    __half h2 = __float2half_rn(w.z), h3 = __float2half_rn(w.w);
    *(__half2*)&g_pwhi[d]     = __halves2half2(h0, h1);
    *(__half2*)&g_pwhi[d + 2] = __halves2half2(h2, h3);
    *(__half2*)&g_pwlo[d]     = __halves2half2(
        __float2half_rn((w.x - __half2float(h0)) * 256.f),
        __float2half_rn((w.y - __half2float(h1)) * 256.f));
    *(__half2*)&g_pwlo[d + 2] = __halves2half2(
        __float2half_rn((w.z - __half2float(h2)) * 256.f),
        __float2half_rn((w.w - __half2float(h3)) * 256.f));
    if (threadIdx.x == 0) g_pb[cn] = bih[orow] + bhh[orow];
}

// ---------------- fused gates MMA + LSTM (4-stage pipeline) ------------------
__global__ void __launch_bounds__(256, 1)
k_gatelstm(int t) {
    extern __shared__ char dsm[];
    const u32 smem0 = smem_u32(dsm);
    const u32 base  = (smem0 + 1023) & ~1023u;
    char* dbase = dsm + (base - smem0);
    int*   stok  = (int*)dbase;
    float* biasG = (float*)(dbase + 256);
    float* sg    = (float*)(dbase + GHDR);       // overlay buf0
    const u32 sbase = base + GHDR;

    const int tid  = threadIdx.x;
    const int wid  = tid >> 5;
    const int lane = tid & 31;
    const int wm   = wid >> 1;
    const int wn   = wid & 1;
    const int cta  = blockIdx.x;
    const int rp   = t & 1;
    const int wp   = rp ^ 1;

    if (cta == 0 && tid < BB) g_ccnt[tid] = 0;   // reset candidate counts
    if (tid < BB) stok[tid] = g_tok[tid];
    if (tid < 32) biasG[tid] = g_pb[cta * 32 + tid];
    __syncthreads();

    const int arow = tid >> 2, aq = (tid & 3) * 2;
    const int brow = tid >> 3, bq = tid & 7;
    auto fill = [&](int ch) {
        const int kb = ch * 64;
        const u32 buf = sbase + (ch & 3) * GBUF;
        #pragma unroll
        for (int i = 0; i < 2; i++) {
            int kq = aq + i;
            u32 sw = SWZ((u32)(arow * 128 + kq * 16));
            if (kb < 512) {
                const size_t s = (size_t)stok[arow] * EMBD + kb + kq * 8;
                cpa16(buf + GAHI + sw, g_ehi + s);
                cpa16(buf + GALO + sw, g_elo + s);
            } else {
                const size_t s = (size_t)arow * HID + (kb - 512) + kq * 8;
                cpa16(buf + GAHI + sw, g_hhb[rp] + s);
                cpa16(buf + GALO + sw, g_hlb[rp] + s);
            }
        }
        {
            u32 sw = SWZ((u32)(brow * 128 + bq * 16));
            const size_t s = (size_t)(cta * 32 + brow) * 1536 + kb + bq * 8;
            cpa16(buf + GBHI + sw, g_pwhi + s);
            cpa16(buf + GBLO + sw, g_pwlo + s);
        }
        CPA_COMMIT();
    };

    float D0[2][4], D1[2][4];
    #pragma unroll
    for (int h = 0; h < 2; h++)
        #pragma unroll
        for (int cc = 0; cc < 4; cc++) { D0[h][cc] = 0.f; D1[h][cc] = 0.f; }

    const int aRow = (lane & 7) + ((lane & 8) ? 8 : 0);
    const int aCol = (lane & 16) ? 16 : 0;
    const int bRow = (lane & 7) + ((lane & 16) ? 8 : 0);
    const int bCol = (lane & 8) ? 16 : 0;

    fill(0); fill(1); fill(2);

    for (int ch = 0; ch < NCHG; ch++) {
        const int rem = NCHG - 1 - ch;
        if (rem >= 2) CPA_WAIT2(); else if (rem == 1) CPA_WAIT1(); else CPA_WAIT0();
        __syncthreads();
        if (ch + 3 < NCHG) fill(ch + 3);
        const u32 buf = sbase + (ch & 3) * GBUF;
        #pragma unroll
        for (int k16 = 0; k16 < 4; k16++) {
            const int kkb = k16 * 32;
            u32 ahi[4], alo[4], bhi[4], blo[4];
            u32 offA = SWZ((u32)((16 * wm + aRow) * 128 + kkb + aCol));
            ldm4(ahi, buf + GAHI + offA);
            ldm4(alo, buf + GALO + offA);
            u32 offB = SWZ((u32)((16 * wn + bRow) * 128 + kkb + bCol));
            ldm4(bhi, buf + GBHI + offB);
            ldm4(blo, buf + GBLO + offB);
            #pragma unroll
            for (int h = 0; h < 2; h++) {
                mma16816(D0[h], ahi, &bhi[2 * h]);
                mma16816(D1[h], ahi, &blo[2 * h]);
                mma16816(D1[h], alo, &bhi[2 * h]);
            }
        }
    }
    __syncthreads();       // all ldmatrix done before sg overlays buf0

    const int q  = lane >> 2;
    const int c2 = (lane & 3) * 2;
    {
        int r0 = 16 * wm + q;
        int r1 = r0 + 8;
        #pragma unroll
        for (int h = 0; h < 2; h++) {
            int c = 16 * wn + 8 * h + c2;
            float b0 = biasG[c], b1 = biasG[c + 1];
            sg[r0 * 33 + c]     = D0[h][0] + D1[h][0] * INV256 + b0;
            sg[r0 * 33 + c + 1] = D0[h][1] + D1[h][1] * INV256 + b1;
            sg[r1 * 33 + c]     = D0[h][2] + D1[h][2] * INV256 + b0;
            sg[r1 * 33 + c + 1] = D0[h][3] + D1[h][3] * INV256 + b1;
        }
    }
    __syncthreads();

    {
        const int row = tid >> 2;
        const int j0 = (tid & 3) * 2;
        const float* sgp = sg + row * 33;
        #pragma unroll
        for (int i = 0; i < 2; i++) {
            int j = j0 + i;
            float gi = sgp[j];
            float gf = sgp[8 + j];
            float gg = sgp[16 + j];
            float go = sgp[24 + j];
            float ig = 1.f / (1.f + expf(-gi));
            float fg = 1.f / (1.f + expf(-gf));
            float gt = tanhf(gg);
            float og = 1.f / (1.f + expf(-go));
            int idx = row * HID + cta * 8 + j;
            float cv = fg * g_c[idx] + ig * gt;
            float hv = og * tanhf(cv);
            g_c[idx] = cv;
            g_hf[idx] = hv;
            __half hh = __float2half_rn(hv);
            g_hhb[wp][idx] = hh;
            g_hlb[wp][idx] = __float2half_rn((hv - __half2float(hh)) * 256.0f);
        }
    }
}

// ---------------- logits: (Ahi + Alo/256) x Bhi, 3-stage, cand collect ------
__global__ void __launch_bounds__(256, 1)
k_logits(const float* __restrict__ fcb, float* __restrict__ out, int t) {
    extern __shared__ char dsm[];
    const u32 smem0 = smem_u32(dsm);
    const u32 base  = (smem0 + 1023) & ~1023u;
    char* dbase = dsm + (base - smem0);
    float* biasF = (float*)dbase;               // 256
    float* spv   = (float*)(dbase + 1024);      // [64][8]
    float* brmax = (float*)(dbase + 3072);      // [64]
    const u32 sbase = base + HDR;

    const int tid  = threadIdx.x;
    const int wn   = tid >> 5;        // warp 0..7 -> cols 32*wn..+31
    const int lane = tid & 31;
    const int v0   = blockIdx.x * 256;
    const int hp   = (t & 1) ^ 1;

    biasF[tid] = fcb[v0 + tid];

    const int frow = tid >> 3, fkq = tid & 7;
    auto fill = [&](int ch) {
        const int kb = ch * 64;
        const u32 buf = sbase + (ch % 3) * BUFSTR;
        #pragma unroll
        for (int i = 0; i < 2; i++) {
            int row = frow + i * 32;
            u32 sw = SWZ((u32)(row * 128 + fkq * 16));
            cpa16(buf + AHI_OFF + sw, g_hhb[hp] + row * HID + kb + fkq * 8);
            cpa16(buf + ALO_OFF + sw, g_hlb[hp] + row * HID + kb + fkq * 8);
        }
        #pragma unroll
        for (int i = 0; i < 8; i++) {
            int row = frow + i * 32;
            u32 sw = SWZ((u32)(row * 128 + fkq * 16));
            cpa16(buf + BHI_OFF + sw, g_whi + (size_t)(v0 + row) * HID + kb + fkq * 8);
        }
        CPA_COMMIT();
    };

    float D0[4][4][4], D1[4][4][4];
    #pragma unroll
    for (int a = 0; a < 4; a++)
        #pragma unroll
        for (int b = 0; b < 4; b++)
            #pragma unroll
            for (int c = 0; c < 4; c++) { D0[a][b][c] = 0.f; D1[a][b][c] = 0.f; }

    const int aRow = (lane & 7) + ((lane & 8) ? 8 : 0);
    const int aCol = (lane & 16) ? 16 : 0;
    const int bRow = (lane & 7) + ((lane & 16) ? 8 : 0);
    const int bCol = (lane & 8) ? 16 : 0;

    fill(0); fill(1);

    for (int ch = 0; ch < NCHUNK; ch++) {
        const int rem = NCHUNK - 1 - ch;
        if (rem >= 1) CPA_WAIT1(); else CPA_WAIT0();
        __syncthreads();
        if (ch + 2 < NCHUNK) fill(ch + 2);
        const u32 buf = sbase + (ch % 3) * BUFSTR;
        #pragma unroll
        for (int k16 = 0; k16 < 4; k16++) {
            const int kkb = k16 * 32;
            u32 ahi[4][4], alo[4][4];
            #pragma unroll
            for (int tm = 0; tm < 4; tm++) {
                u32 off = SWZ((u32)((16 * tm + aRow) * 128 + kkb + aCol));
                ldm4(ahi[tm], buf + AHI_OFF + off);
                ldm4(alo[tm], buf + ALO_OFF + off);
            }
            #pragma unroll
            for (int g = 0; g < 2; g++) {
                u32 off = SWZ((u32)((32 * wn + 16 * g + bRow) * 128 + kkb + bCol));
                u32 bhi[4];
                ldm4(bhi, buf + BHI_OFF + off);
                #pragma unroll
                for (int tm = 0; tm < 4; tm++) {
                    #pragma unroll
                    for (int h = 0; h < 2; h++) {
                        int tn = 2 * g + h;
                        mma16816(D0[tm][tn], ahi[tm], &bhi[2 * h]);
                        mma16816(D1[tm][tn], alo[tm], &bhi[2 * h]);
                    }
                }
            }
        }
    }

    // epilogue: combine, bias, store, per-warp row max -> cross-warp reduce
    const int q  = lane >> 2;
    const int c2 = (lane & 3) * 2;
    float mv[8];
    #pragma unroll
    for (int s = 0; s < 8; s++) mv[s] = -3.4e38f;
    #pragma unroll
    for (int tm = 0; tm < 4; tm++) {
        int r0 = 16 * tm + q;
        int r1 = r0 + 8;
        float* p0 = out + (size_t)r0 * TSTEPS * VOC + (size_t)t * VOC + v0;
        float* p1 = out + (size_t)r1 * TSTEPS * VOC + (size_t)t * VOC + v0;
        const int s0 = 2 * tm, s1 = 2 * tm + 1;
        #pragma unroll
        for (int tn = 0; tn < 4; tn++) {
            int c = 32 * wn + 8 * tn + c2;
            float b0 = biasF[c], b1 = biasF[c + 1];
            float v00 = D0[tm][tn][0] + D1[tm][tn][0] * INV256 + b0;
            float v01 = D0[tm][tn][1] + D1[tm][tn][1] * INV256 + b1;
            float v10 = D0[tm][tn][2] + D1[tm][tn][2] * INV256 + b0;
            float v11 = D0[tm][tn][3] + D1[tm][tn][3] * INV256 + b1;
            *(float2*)&p0[c] = make_float2(v00, v01);
            *(float2*)&p1[c] = make_float2(v10, v11);
            mv[s0] = fmaxf(mv[s0], fmaxf(v00, v01));
            mv[s1] = fmaxf(mv[s1], fmaxf(v10, v11));
        }
    }
    #pragma unroll
    for (int off = 1; off <= 2; off <<= 1) {
        #pragma unroll
        for (int s = 0; s < 8; s++)
            mv[s] = fmaxf(mv[s], __shfl_xor_sync(0xffffffffu, mv[s], off));
    }
    if ((lane & 3) == 0) {
        #pragma unroll
        for (int s = 0; s < 8; s++) {
            int row = 16 * (s >> 1) + 8 * (s & 1) + q;
            spv[row * 8 + wn] = mv[s];
        }
    }
    __syncthreads();
    if (tid < 64) {
        float bv = spv[tid * 8];
        #pragma unroll
        for (int j = 1; j < 8; j++) bv = fmaxf(bv, spv[tid * 8 + j]);
        g_pval[tid * NLBLK + blockIdx.x] = bv;
        brmax[tid] = bv;
    }
    __syncthreads();

    // candidate collection: warp wn handles rows 8*wn..8*wn+7 (L2-hot re-read)
    #pragma unroll
    for (int i = 0; i < 8; i++) {
        int row = wn * 8 + i;
        float thr = brmax[row] - 0.05f;
        const float* orow = out + (size_t)row * TSTEPS * VOC + (size_t)t * VOC + v0;
        #pragma unroll
        for (int j = 0; j < 8; j++) {
            int c = lane + 32 * j;
            float v = orow[c];
            if (v >= thr) {
                int s = atomicAdd(&g_ccnt[row], 1);
                if (s < CAP2) { g_cidx[row][s] = v0 + c; g_cval[row][s] = v; }
            }
        }
    }
}

// ---------------- refine: candidate-based exact argmax (no scans) -----------
__global__ void __launch_bounds__(128, 1)
k_refine(const float* __restrict__ fcw, const float* __restrict__ fcb, int t) {
    __shared__ float sh[HID];
    __shared__ float smax[4];
    __shared__ int   fidx[64];
    __shared__ float sval[64];
    __shared__ int   fcnt;
    const int r = blockIdx.x;
    const int tid = threadIdx.x, wid = tid >> 5, lane = tid & 31;

    #pragma unroll
    for (int i = 0; i < 2; i++)
        ((float4*)sh)[tid * 2 + i] = ((const float4*)(g_hf + r * HID))[tid * 2 + i];
    if (tid == 0) fcnt = 0;

    // gm over 125 block maxima
    float m = -3.4e38f;
    for (int b = tid; b < NLBLK; b += 128) m = fmaxf(m, g_pval[r * NLBLK + b]);
    #pragma unroll
    for (int off = 16; off; off >>= 1) m = fmaxf(m, __shfl_xor_sync(0xffffffffu, m, off));
    if (lane == 0) smax[wid] = m;
    __syncthreads();
    float gm = fmaxf(fmaxf(smax[0], smax[1]), fmaxf(smax[2], smax[3]));
    const float thr = gm - 0.04f;     // rigorous 2*delta ~ 0.02, 2x slack

    // filter candidates
    int n = g_ccnt[r]; if (n > CAP2) n = CAP2;
    for (int k = tid; k < n; k += 128) {
        if (g_cval[r][k] >= thr) {
            int s = atomicAdd(&fcnt, 1);
            if (s < 64) fidx[s] = g_cidx[r][k];
        }
    }
    __syncthreads();
    int nf = fcnt < 64 ? fcnt : 64;

    // exact fp32 rescoring (one warp per survivor)
    for (int k = wid; k < nf; k += 4) {
        int c = fidx[k];
        const float4* wr = (const float4*)(fcw + (size_t)c * HID);
        const float4* hr = (const float4*)sh;
        float s = 0.f;
        #pragma unroll
        for (int qq = 0; qq < 8; qq++) {
            float4 wv = wr[qq * 32 + lane];
            float4 hv = hr[qq * 32 + lane];
            s += wv.x * hv.x + wv.y * hv.y + wv.z * hv.z + wv.w * hv.w;
        }
        #pragma unroll
        for (int off = 16; off; off >>= 1) s += __shfl_xor_sync(0xffffffffu, s, off);
        if (lane == 0) sval[k] = s + fcb[c];
    }
    __syncthreads();
    if (tid == 0) {
        float bv = -3.4e38f; int bi = 0x7fffffff;
        for (int k = 0; k < nf; k++) {
            float vv = sval[k]; int c = fidx[k];
            if (vv > bv || (vv == bv && c < bi)) { bv = vv; bi = c; }
        }
        g_tok[r] = bi;
    }
}

// ---------------- launch -----------------------------------------------------
extern "C" void kernel_launch(void* const* d_in, const int* in_sizes, int n_in,
                              void* d_out, int out_size) {
    const float* z   = (const float*)d_in[0];
    const float* emb = (const float*)d_in[1];
    const float* wih = (const float*)d_in[2];
    const float* whh = (const float*)d_in[3];
    const float* bih = (const float*)d_in[4];
    const float* bhh = (const float*)d_in[5];
    const float* fcw = (const float*)d_in[6];
    const float* fcb = (const float*)d_in[7];
    const float* lw  = (const float*)d_in[8];
    const float* lb  = (const float*)d_in[9];
    float* out = (float*)d_out;

    static int smem_set = 0;
    if (!smem_set) {
        cudaFuncSetAttribute(k_logits,   cudaFuncAttributeMaxDynamicSharedMemorySize, DSMEM);
        cudaFuncSetAttribute(k_gatelstm, cudaFuncAttributeMaxDynamicSharedMemorySize, GDSM);
        smem_set = 1;
    }

    k_init<<<256, 256>>>(z, lw, lb);                 // launch 0
    k_prepA<<<48000, 256>>>(fcw, emb);               // launch 1
    k_prepB<<<4096, 384>>>(wih, whh, bih, bhh);      // launch 2
    for (int t = 0; t < TSTEPS; t++) {
        k_gatelstm<<<128, 256, GDSM>>>(t);           // launch 3 (t=0) <- ncu
        k_logits<<<NLBLK, 256, DSMEM>>>(fcb, out, t);
        if (t < TSTEPS - 1) k_refine<<<BB, 128>>>(fcw, fcb, t);
    }
}

// round 12
// speedup vs baseline: 1.3502x; 1.3502x over previous
#include <cuda_runtime.h>
#include <cuda_fp16.h>
#include <math.h>

#define BB     64
#define LATENT 128
#define EMBD   512
#define HID    1024
#define VOC    32000
#define TSTEPS 64
#define NLBLK  125          // logits CTAs (125 * 256 = 32000)
#define NCHUNK 16           // logits K chunks of 64 halves
#define NCHG   24           // gates K chunks (1536/64)
#define NCHGH  12           // gates chunks per warp-group
#define INV256 0.00390625f

typedef unsigned long long u64;
typedef unsigned int u32;

// ---------------- device state (no allocation) ------------------------------
__device__ float g_c[BB * HID];
__device__ float g_pval[BB * NLBLK];                       // per-block row max
__device__ int   g_tok[BB];
__device__ float g_hf[BB * HID];                           // fp32 h (refine)
__device__ __align__(16) __half g_hhb[2][BB * HID];        // h hi ping-pong
__device__ __align__(16) __half g_hlb[2][BB * HID];        // h lo ping-pong
__device__ __align__(16) __half g_whi[(size_t)VOC * HID];  // fc_w hi
__device__ __align__(16) __half g_ehi[(size_t)VOC * EMBD]; // emb hi
__device__ __align__(16) __half g_elo[(size_t)VOC * EMBD]; // emb lo*256
__device__ __align__(16) __half g_pwhi[4096 * 1536];       // packed gate W hi
__device__ __align__(16) __half g_pwlo[4096 * 1536];       // packed gate W lo*256
__device__ float g_pb[4096];                               // packed bih+bhh

// ---------------- helpers ---------------------------------------------------
__device__ __forceinline__ u32 smem_u32(const void* p) {
    u32 a; asm("{ .reg .u64 t; cvta.to.shared.u64 t, %1; cvt.u32.u64 %0, t; }"
               : "=r"(a) : "l"(p));
    return a;
}
__device__ __forceinline__ void cpa16(u32 dst, const void* src) {
    asm volatile("cp.async.cg.shared.global [%0], [%1], 16;" :: "r"(dst), "l"(src));
}
#define CPA_COMMIT() asm volatile("cp.async.commit_group;" ::: "memory")
#define CPA_WAIT0()  asm volatile("cp.async.wait_group 0;" ::: "memory")
#define BARG(id)     asm volatile("bar.sync %0, 256;" :: "r"(id) : "memory")

__device__ __forceinline__ void ldm4(u32* r, u32 addr) {
    asm volatile("ldmatrix.sync.aligned.m8n8.x4.shared.b16 {%0,%1,%2,%3}, [%4];"
        : "=r"(r[0]), "=r"(r[1]), "=r"(r[2]), "=r"(r[3]) : "r"(addr));
}
__device__ __forceinline__ void mma16816(float* d, const u32* a, const u32* b) {
    asm volatile("mma.sync.aligned.m16n8k16.row.col.f32.f16.f16.f32 "
        "{%0,%1,%2,%3}, {%4,%5,%6,%7}, {%8,%9}, {%0,%1,%2,%3};"
        : "+f"(d[0]), "+f"(d[1]), "+f"(d[2]), "+f"(d[3])
        : "r"(a[0]), "r"(a[1]), "r"(a[2]), "r"(a[3]), "r"(b[0]), "r"(b[1]));
}

#define SWZ(o) ((o) ^ (((o) >> 3) & 0x70))

// logits SMEM (R10-exact): hdr 4096 (bias 1024 | spv 2048) + 2 buffers of 48K
#define AHI_OFF  0
#define ALO_OFF  8192
#define BHI_OFF  16384
#define BUFSTR   49152
#define HDR      4096
#define DSMEM    (1024 + HDR + 2 * BUFSTR)

// gates SMEM: hdr 512 (stok 256 | bias 128) + 4 buffers of 24K (2 per group)
#define GAHI 0
#define GALO 8192
#define GBHI 16384
#define GBLO 20480
#define GBUF 24576
#define GHDR 512
#define GDSM (1024 + GHDR + 4 * GBUF)

// ---------------- init: h = z @ lth_w^T + lth_b -> buf 0 --------------------
__global__ void k_init(const float* __restrict__ z,
                       const float* __restrict__ lw,
                       const float* __restrict__ lb) {
    int idx = blockIdx.x * 256 + threadIdx.x;
    int r = idx >> 10;
    int u = idx & (HID - 1);
    float s = lb[u];
    const float* zr = z + r * LATENT;
    const float* wr = lw + (size_t)u * LATENT;
    #pragma unroll 8
    for (int k = 0; k < LATENT; k++) s += zr[k] * wr[k];
    g_c[idx] = 0.f;
    __half hh = __float2half_rn(s);
    g_hhb[0][idx] = hh;
    g_hlb[0][idx] = __float2half_rn((s - __half2float(hh)) * 256.0f);
    if (idx < BB) g_tok[idx] = 0;
}

// ---------------- prep A: fc_w hi + emb hi/lo --------------------------------
__global__ void __launch_bounds__(256, 1)
k_prepA(const float* __restrict__ fcw, const float* __restrict__ emb) {
    const int bid = blockIdx.x;
    const int tid = threadIdx.x;
    if (bid < 32000) {
        size_t i4 = (size_t)bid * 1024 + tid * 4;
        float4 w = *(const float4*)&fcw[i4];
        *(__half2*)&g_whi[i4]     = __halves2half2(__float2half_rn(w.x), __float2half_rn(w.y));
        *(__half2*)&g_whi[i4 + 2] = __halves2half2(__float2half_rn(w.z), __float2half_rn(w.w));
    } else {
        size_t i4 = (size_t)(bid - 32000) * 1024 + tid * 4;
        float4 w = *(const float4*)&emb[i4];
        __half h0 = __float2half_rn(w.x), h1 = __float2half_rn(w.y);
        __half h2 = __float2half_rn(w.z), h3 = __float2half_rn(w.w);
        *(__half2*)&g_ehi[i4]     = __halves2half2(h0, h1);
        *(__half2*)&g_ehi[i4 + 2] = __halves2half2(h2, h3);
        *(__half2*)&g_elo[i4]     = __halves2half2(
            __float2half_rn((w.x - __half2float(h0)) * 256.f),
            __float2half_rn((w.y - __half2float(h1)) * 256.f));
        *(__half2*)&g_elo[i4 + 2] = __halves2half2(
            __float2half_rn((w.z - __half2float(h2)) * 256.f),
            __float2half_rn((w.w - __half2float(h3)) * 256.f));
    }
}

// ---------------- prep B: packed gate weights + bias -------------------------
__global__ void __launch_bounds__(384, 1)
k_prepB(const float* __restrict__ wih, const float* __restrict__ whh,
        const float* __restrict__ bih, const float* __restrict__ bhh) {
    int cn = blockIdx.x;                 // 0..4095
    int c = cn >> 5, n = cn & 31;
    int g = n >> 3, j = n & 7;
    int orow = g * 1024 + c * 8 + j;
    int k0 = threadIdx.x * 4;            // 0..1532
    float4 w = (k0 < 512)
        ? *(const float4*)&wih[(size_t)orow * EMBD + k0]
        : *(const float4*)&whh[(size_t)orow * HID + k0 - 512];
    size_t d = (size_t)cn * 1536 + k0;
    __half h0 = __float2half_rn(w.x), h1 = __float2half_rn(w.y);
    __half h2 = __float2half_rn(w.z), h3 = __float2half_rn(w.w);
    *(__half2*)&g_pwhi[d]     = __halves2half2(h0, h1);
    *(__half2*)&g_pwhi[d + 2] = __halves2half2(h2, h3);
    *(__half2*)&g_pwlo[d]     = __halves2half2(
        __float2half_rn((w.x - __half2float(h0)) * 256.f),
        __float2half_rn((w.y - __half2float(h1)) * 256.f));
    *(__half2*)&g_pwlo[d + 2] = __halves2half2(
        __float2half_rn((w.z - __half2float(h2)) * 256.f),
        __float2half_rn((w.w - __half2float(h3)) * 256.f));
    if (threadIdx.x == 0) g_pb[cn] = bih[orow] + bhh[orow];
}

// ---------------- fused gates MMA + LSTM: 512 thr, K-split warp groups ------
// Group g (warps 8g..8g+7) processes chunks [12g, 12g+12) in its own
// double-buffer with named-barrier pipeline; partials combined in smem.
__global__ void __launch_bounds__(512, 1)
k_gatelstm(int t) {
    extern __shared__ char dsm[];
    const u32 smem0 = smem_u32(dsm);
    const u32 base  = (smem0 + 1023) & ~1023u;
    char* dbase = dsm + (base - smem0);
    int*   stok  = (int*)dbase;
    float* biasG = (float*)(dbase + 256);
    float* sg    = (float*)(dbase + GHDR);       // overlay buf0: [2][64][33]
    const u32 sbase = base + GHDR;

    const int tid  = threadIdx.x;
    const int lane = tid & 31;
    const int grp  = tid >> 8;        // 0..1 warp group
    const int gtid = tid & 255;
    const int gwid = (tid >> 5) & 7;
    const int wm   = gwid >> 1;       // 0..3 (16 M-rows each)
    const int wn   = gwid & 1;        // 0..1 (16 N-cols each)
    const int cta  = blockIdx.x;
    const int rp   = t & 1;
    const int wp   = rp ^ 1;
    const int c0g  = grp * NCHGH;     // first chunk of this group

    if (tid < BB) stok[tid] = g_tok[tid];
    if (tid < 32) biasG[tid] = g_pb[cta * 32 + tid];
    __syncthreads();

    const int arow = gtid >> 2, aq = (gtid & 3) * 2;
    const int brow = gtid >> 3, bq = gtid & 7;
    auto fill = [&](int ch) {
        const int kb = ch * 64;
        const u32 buf = sbase + (grp * 2 + (ch & 1)) * GBUF;
        #pragma unroll
        for (int i = 0; i < 2; i++) {
            int kq = aq + i;
            u32 sw = SWZ((u32)(arow * 128 + kq * 16));
            if (kb < 512) {
                const size_t s = (size_t)stok[arow] * EMBD + kb + kq * 8;
                cpa16(buf + GAHI + sw, g_ehi + s);
                cpa16(buf + GALO + sw, g_elo + s);
            } else {
                const size_t s = (size_t)arow * HID + (kb - 512) + kq * 8;
                cpa16(buf + GAHI + sw, g_hhb[rp] + s);
                cpa16(buf + GALO + sw, g_hlb[rp] + s);
            }
        }
        {
            u32 sw = SWZ((u32)(brow * 128 + bq * 16));
            const size_t s = (size_t)(cta * 32 + brow) * 1536 + kb + bq * 8;
            cpa16(buf + GBHI + sw, g_pwhi + s);
            cpa16(buf + GBLO + sw, g_pwlo + s);
        }
        CPA_COMMIT();
    };

    float D0[2][4], D1[2][4];
    #pragma unroll
    for (int h = 0; h < 2; h++)
        #pragma unroll
        for (int cc = 0; cc < 4; cc++) { D0[h][cc] = 0.f; D1[h][cc] = 0.f; }

    const int aRow = (lane & 7) + ((lane & 8) ? 8 : 0);
    const int aCol = (lane & 16) ? 16 : 0;
    const int bRow = (lane & 7) + ((lane & 16) ? 8 : 0);
    const int bCol = (lane & 8) ? 16 : 0;

    fill(c0g);
    CPA_WAIT0();
    BARG(1 + grp);

    for (int i = 0; i < NCHGH; i++) {
        const int ch = c0g + i;
        if (i + 1 < NCHGH) fill(ch + 1);
        const u32 buf = sbase + (grp * 2 + (ch & 1)) * GBUF;
        #pragma unroll
        for (int k16 = 0; k16 < 4; k16++) {
            const int kkb = k16 * 32;
            u32 ahi[4], alo[4], bhi[4], blo[4];
            u32 offA = SWZ((u32)((16 * wm + aRow) * 128 + kkb + aCol));
            ldm4(ahi, buf + GAHI + offA);
            ldm4(alo, buf + GALO + offA);
            u32 offB = SWZ((u32)((16 * wn + bRow) * 128 + kkb + bCol));
            ldm4(bhi, buf + GBHI + offB);
            ldm4(blo, buf + GBLO + offB);
            #pragma unroll
            for (int h = 0; h < 2; h++) {
                mma16816(D0[h], ahi, &bhi[2 * h]);
                mma16816(D1[h], ahi, &blo[2 * h]);
                mma16816(D1[h], alo, &bhi[2 * h]);
            }
        }
        if (i + 1 < NCHGH) { CPA_WAIT0(); BARG(1 + grp); }
    }
    __syncthreads();       // both groups done with all ldmatrix before overlay

    // deposit partials: sg[grp][64][33]; group 0 adds bias
    const int q  = lane >> 2;
    const int c2 = (lane & 3) * 2;
    {
        float* sgp = sg + grp * (64 * 33);
        int r0 = 16 * wm + q;
        int r1 = r0 + 8;
        #pragma unroll
        for (int h = 0; h < 2; h++) {
            int c = 16 * wn + 8 * h + c2;
            float b0 = grp ? 0.f : biasG[c];
            float b1 = grp ? 0.f : biasG[c + 1];
            sgp[r0 * 33 + c]     = D0[h][0] + D1[h][0] * INV256 + b0;
            sgp[r0 * 33 + c + 1] = D0[h][1] + D1[h][1] * INV256 + b1;
            sgp[r1 * 33 + c]     = D0[h][2] + D1[h][2] * INV256 + b0;
            sgp[r1 * 33 + c + 1] = D0[h][3] + D1[h][3] * INV256 + b1;
        }
    }
    __syncthreads();

    // LSTM pointwise: 512 threads, one unit each (row = tid>>3, j = tid&7)
    {
        const int row = tid >> 3;
        const int j   = tid & 7;
        const float* s0 = sg + row * 33;
        const float* s1 = sg + 64 * 33 + row * 33;
        float gi = s0[j]      + s1[j];
        float gf = s0[8 + j]  + s1[8 + j];
        float gg = s0[16 + j] + s1[16 + j];
        float go = s0[24 + j] + s1[24 + j];
        float ig = 1.f / (1.f + expf(-gi));
        float fg = 1.f / (1.f + expf(-gf));
        float gt = tanhf(gg);
        float og = 1.f / (1.f + expf(-go));
        int idx = row * HID + cta * 8 + j;
        float cv = fg * g_c[idx] + ig * gt;
        float hv = og * tanhf(cv);
        g_c[idx] = cv;
        g_hf[idx] = hv;
        __half hh = __float2half_rn(hv);
        g_hhb[wp][idx] = hh;
        g_hlb[wp][idx] = __float2half_rn((hv - __half2float(hh)) * 256.0f);
    }
}

// ---------------- logits: R10-exact (Ahi + Alo/256) x Bhi, 64x32 tiles ------
__global__ void __launch_bounds__(256, 1)
k_logits(const float* __restrict__ fcb, float* __restrict__ out, int t) {
    extern __shared__ char dsm[];
    const u32 smem0 = smem_u32(dsm);
    const u32 base  = (smem0 + 1023) & ~1023u;
    char* dbase = dsm + (base - smem0);
    float* biasF = (float*)dbase;               // 256
    float* spv   = (float*)(dbase + 1024);      // [64][8]
    const u32 sbase = base + HDR;

    const int tid  = threadIdx.x;
    const int wn   = tid >> 5;        // warp 0..7 -> cols 32*wn..+31
    const int lane = tid & 31;
    const int v0   = blockIdx.x * 256;
    const int hp   = (t & 1) ^ 1;

    biasF[tid] = fcb[v0 + tid];

    const int frow = tid >> 3, fkq = tid & 7;
    auto fill = [&](int ch, int b) {
        const int kb = ch * 64;
        const u32 buf = sbase + b * BUFSTR;
        #pragma unroll
        for (int i = 0; i < 2; i++) {
            int row = frow + i * 32;
            u32 sw = SWZ((u32)(row * 128 + fkq * 16));
            cpa16(buf + AHI_OFF + sw, g_hhb[hp] + row * HID + kb + fkq * 8);
            cpa16(buf + ALO_OFF + sw, g_hlb[hp] + row * HID + kb + fkq * 8);
        }
        #pragma unroll
        for (int i = 0; i < 8; i++) {
            int row = frow + i * 32;
            u32 sw = SWZ((u32)(row * 128 + fkq * 16));
            cpa16(buf + BHI_OFF + sw, g_whi + (size_t)(v0 + row) * HID + kb + fkq * 8);
        }
        CPA_COMMIT();
    };

    float D0[4][4][4], D1[4][4][4];            // [tm][tn][frag]
    #pragma unroll
    for (int a = 0; a < 4; a++)
        #pragma unroll
        for (int b = 0; b < 4; b++)
            #pragma unroll
            for (int c = 0; c < 4; c++) { D0[a][b][c] = 0.f; D1[a][b][c] = 0.f; }

    const int aRow = (lane & 7) + ((lane & 8) ? 8 : 0);
    const int aCol = (lane & 16) ? 16 : 0;
    const int bRow = (lane & 7) + ((lane & 16) ? 8 : 0);
    const int bCol = (lane & 8) ? 16 : 0;

    fill(0, 0);
    CPA_WAIT0();
    __syncthreads();

    for (int ch = 0; ch < NCHUNK; ch++) {
        const int b = ch & 1;
        if (ch + 1 < NCHUNK) fill(ch + 1, b ^ 1);
        const u32 buf = sbase + b * BUFSTR;
        #pragma unroll
        for (int k16 = 0; k16 < 4; k16++) {
            const int kkb = k16 * 32;
            u32 ahi[4][4], alo[4][4];
            #pragma unroll
            for (int tm = 0; tm < 4; tm++) {
                u32 off = SWZ((u32)((16 * tm + aRow) * 128 + kkb + aCol));
                ldm4(ahi[tm], buf + AHI_OFF + off);
                ldm4(alo[tm], buf + ALO_OFF + off);
            }
            #pragma unroll
            for (int g = 0; g < 2; g++) {
                u32 off = SWZ((u32)((32 * wn + 16 * g + bRow) * 128 + kkb + bCol));
                u32 bhi[4];
                ldm4(bhi, buf + BHI_OFF + off);
                #pragma unroll
                for (int tm = 0; tm < 4; tm++) {
                    #pragma unroll
                    for (int h = 0; h < 2; h++) {
                        int tn = 2 * g + h;
                        mma16816(D0[tm][tn], ahi[tm], &bhi[2 * h]);
                        mma16816(D1[tm][tn], alo[tm], &bhi[2 * h]);
                    }
                }
            }
        }
        if (ch + 1 < NCHUNK) { CPA_WAIT0(); __syncthreads(); }
    }

    // epilogue: combine, bias, store, per-warp row max -> cross-warp reduce
    const int q  = lane >> 2;
    const int c2 = (lane & 3) * 2;
    float mv[8];
    #pragma unroll
    for (int s = 0; s < 8; s++) mv[s] = -3.4e38f;
    #pragma unroll
    for (int tm = 0; tm < 4; tm++) {
        int r0 = 16 * tm + q;
        int r1 = r0 + 8;
        float* p0 = out + (size_t)r0 * TSTEPS * VOC + (size_t)t * VOC + v0;
        float* p1 = out + (size_t)r1 * TSTEPS * VOC + (size_t)t * VOC + v0;
        const int s0 = 2 * tm, s1 = 2 * tm + 1;
        #pragma unroll
        for (int tn = 0; tn < 4; tn++) {
            int c = 32 * wn + 8 * tn + c2;
            float b0 = biasF[c], b1 = biasF[c + 1];
            float v00 = D0[tm][tn][0] + D1[tm][tn][0] * INV256 + b0;
            float v01 = D0[tm][tn][1] + D1[tm][tn][1] * INV256 + b1;
            float v10 = D0[tm][tn][2] + D1[tm][tn][2] * INV256 + b0;
            float v11 = D0[tm][tn][3] + D1[tm][tn][3] * INV256 + b1;
            *(float2*)&p0[c] = make_float2(v00, v01);
            *(float2*)&p1[c] = make_float2(v10, v11);
            mv[s0] = fmaxf(mv[s0], fmaxf(v00, v01));
            mv[s1] = fmaxf(mv[s1], fmaxf(v10, v11));
        }
    }
    #pragma unroll
    for (int off = 1; off <= 2; off <<= 1) {
        #pragma unroll
        for (int s = 0; s < 8; s++)
            mv[s] = fmaxf(mv[s], __shfl_xor_sync(0xffffffffu, mv[s], off));
    }
    if ((lane & 3) == 0) {
        #pragma unroll
        for (int s = 0; s < 8; s++) {
            int row = 16 * (s >> 1) + 8 * (s & 1) + q;
            spv[row * 8 + wn] = mv[s];
        }
    }
    __syncthreads();
    if (tid < 64) {
        float bv = spv[tid * 8];
        #pragma unroll
        for (int j = 1; j < 8; j++) bv = fmaxf(bv, spv[tid * 8 + j]);
        g_pval[tid * NLBLK + blockIdx.x] = bv;
    }
}

// ---------------- refine: block-rescan exact argmax --------------------------
// |L_stored - L_true| <= ||h||2 * 2^-12 * ||w_c||2 <= 32/4096 = 0.0078 = delta
// thr = gm - 0.04 (> 2*delta rigorous, 2.5x slack). Only blocks whose max
// clears thr can hold candidates -> rescan just those 256-col slices (L2-hot).
__global__ void __launch_bounds__(128, 1)
k_refine(const float* __restrict__ fcw, const float* __restrict__ fcb,
         const float* __restrict__ out, int t) {
    __shared__ float sh[HID];
    __shared__ float smax[4];
    __shared__ int   sblk[NLBLK];
    __shared__ int   fidx[64];
    __shared__ float sval[64];
    __shared__ int   nb, fcnt;
    const int r = blockIdx.x;
    const int tid = threadIdx.x, wid = tid >> 5, lane = tid & 31;
    const float* row = out + (size_t)r * TSTEPS * VOC + (size_t)t * VOC;

    #pragma unroll
    for (int i = 0; i < 2; i++)
        ((float4*)sh)[tid * 2 + i] = ((const float4*)(g_hf + r * HID))[tid * 2 + i];
    if (tid == 0) { nb = 0; fcnt = 0; }

    float m = -3.4e38f;
    for (int b = tid; b < NLBLK; b += 128) m = fmaxf(m, g_pval[r * NLBLK + b]);
    #pragma unroll
    for (int off = 16; off; off >>= 1) m = fmaxf(m, __shfl_xor_sync(0xffffffffu, m, off));
    if (lane == 0) smax[wid] = m;
    __syncthreads();
    float gm = fmaxf(fmaxf(smax[0], smax[1]), fmaxf(smax[2], smax[3]));
    const float thr = gm - 0.04f;

    // blocks that can contain candidates
    for (int b = tid; b < NLBLK; b += 128)
        if (g_pval[r * NLBLK + b] >= thr) { int i = atomicAdd(&nb, 1); sblk[i] = b; }
    __syncthreads();

    // rescan those blocks' 256 columns for candidates
    for (int bi = 0; bi < nb; bi++) {
        int b = sblk[bi];
        for (int c = tid; c < 256; c += 128) {
            float v = row[b * 256 + c];
            if (v >= thr) {
                int s = atomicAdd(&fcnt, 1);
                if (s < 64) fidx[s] = b * 256 + c;
            }
        }
    }
    __syncthreads();
    int nf = fcnt < 64 ? fcnt : 64;

    // exact fp32 rescoring (one warp per survivor)
    for (int k = wid; k < nf; k += 4) {
        int c = fidx[k];
        const float4* wr = (const float4*)(fcw + (size_t)c * HID);
        const float4* hr = (const float4*)sh;
        float s = 0.f;
        #pragma unroll
        for (int qq = 0; qq < 8; qq++) {
            float4 wv = wr[qq * 32 + lane];
            float4 hv = hr[qq * 32 + lane];
            s += wv.x * hv.x + wv.y * hv.y + wv.z * hv.z + wv.w * hv.w;
        }
        #pragma unroll
        for (int off = 16; off; off >>= 1) s += __shfl_xor_sync(0xffffffffu, s, off);
        if (lane == 0) sval[k] = s + fcb[c];
    }
    __syncthreads();
    if (tid == 0) {
        float bv = -3.4e38f; int bi = 0x7fffffff;
        for (int k = 0; k < nf; k++) {
            float vv = sval[k]; int c = fidx[k];
            if (vv > bv || (vv == bv && c < bi)) { bv = vv; bi = c; }
        }
        g_tok[r] = bi;
    }
}

// ---------------- launch -----------------------------------------------------
extern "C" void kernel_launch(void* const* d_in, const int* in_sizes, int n_in,
                              void* d_out, int out_size) {
    const float* z   = (const float*)d_in[0];
    const float* emb = (const float*)d_in[1];
    const float* wih = (const float*)d_in[2];
    const float* whh = (const float*)d_in[3];
    const float* bih = (const float*)d_in[4];
    const float* bhh = (const float*)d_in[5];
    const float* fcw = (const float*)d_in[6];
    const float* fcb = (const float*)d_in[7];
    const float* lw  = (const float*)d_in[8];
    const float* lb  = (const float*)d_in[9];
    float* out = (float*)d_out;

    static int smem_set = 0;
    if (!smem_set) {
        cudaFuncSetAttribute(k_logits,   cudaFuncAttributeMaxDynamicSharedMemorySize, DSMEM);
        cudaFuncSetAttribute(k_gatelstm, cudaFuncAttributeMaxDynamicSharedMemorySize, GDSM);
        smem_set = 1;
    }

    k_init<<<256, 256>>>(z, lw, lb);                 // launch 0
    k_prepA<<<48000, 256>>>(fcw, emb);               // launch 1
    k_prepB<<<4096, 384>>>(wih, whh, bih, bhh);      // launch 2
    for (int t = 0; t < TSTEPS; t++) {
        k_gatelstm<<<128, 512, GDSM>>>(t);           // launch 3 (t=0) <- ncu
        k_logits<<<NLBLK, 256, DSMEM>>>(fcb, out, t);
        if (t < TSTEPS - 1) k_refine<<<BB, 128>>>(fcw, fcb, out, t);
    }
}